// round 13
// baseline (speedup 1.0000x reference)
#include <cuda_runtime.h>
#include <cstdint>

#define NB    4
#define NPIX  65536     // 256*256
#define CCH   128
#define HF    512
#define WF    512
#define NPTS  8192
#define HID   256
#define NFEAT 129
#define TP    64        // points per tile
#define TT    4         // tiles per block (pipelined)
#define NBIN  65536     // 16-bit radix digit

// ---------------- device scratch (no allocations allowed) ----------------
__device__ unsigned int g_thresh32[NB];   // threshold |v| bitpattern T
__device__ unsigned int g_prefix[NB];     // top-16 bits after pass 1
__device__ int g_target[NB];
__device__ int g_cnt[NB];
__device__ int g_idx[NB * NPTS];
__device__ unsigned int g_hist[NB * NBIN];   // zero at load; scans re-zero

__device__ __forceinline__ unsigned int absbits(float v) {
    return __float_as_uint(v) & 0x7fffffffu;
}

// ---------------- kernel 1: pass-1 histogram (top 16 bits of |v|) --------
// grid (32, NB) x 256; 8 elems/thread, coalesced; global atomics (low cont.)
__global__ void hist1_kernel(const float* __restrict__ coarse) {
    const int b   = blockIdx.y;
    const int tid = threadIdx.x;
    const float* src = coarse + b * NPIX;
    unsigned int* hist = g_hist + b * NBIN;
    const int base = blockIdx.x * 2048;
    #pragma unroll
    for (int j = 0; j < 8; j++)
        atomicAdd(&hist[absbits(src[base + j * 256 + tid]) >> 16], 1u);
}

// ---------------- kernel 3: pass-2 histogram (low 16 bits, filtered) -----
__global__ void hist2_kernel(const float* __restrict__ coarse) {
    const int b   = blockIdx.y;
    const int tid = threadIdx.x;
    const unsigned int pref = g_prefix[b];
    const float* src = coarse + b * NPIX;
    unsigned int* hist = g_hist + b * NBIN;
    const int base = blockIdx.x * 2048;
    #pragma unroll
    for (int j = 0; j < 8; j++) {
        const unsigned int a = absbits(src[base + j * 256 + tid]);
        if ((a >> 16) == pref) atomicAdd(&hist[a & 0xffffu], 1u);
    }
}

// ---------------- kernels 2&4: scan 64K bins, locate, zero ----------------
// grid NB x 1024; 64 bins per thread (16 x uint4). pass==2 additionally
// resolves threshold ties EXACTLY: the first-by-index `need` elements with
// absbits==T are written into the tail of g_idx (positions NPTS-need ..
// NPTS-1), index-ordered via a per-thread 64-bit match mask + block scan.
// compact fills positions 0 .. NPTS-need-1 with all absbits < T.
__global__ void scan_kernel(const float* __restrict__ coarse, int pass) {
    __shared__ unsigned int ssum[1024];
    __shared__ unsigned int s_T;
    __shared__ int s_need;
    const int b   = blockIdx.x;
    const int tid = threadIdx.x;
    uint4* hist4 = reinterpret_cast<uint4*>(g_hist + b * NBIN);

    // sum this thread's 64 bins (16 uint4), values discarded after summing
    unsigned int s = 0;
    #pragma unroll
    for (int q = 0; q < 16; q++) {
        const uint4 h = hist4[tid * 16 + q];
        s += h.x + h.y + h.z + h.w;
    }
    ssum[tid] = s;
    __syncthreads();
    // Hillis-Steele inclusive scan over 1024 partials
    for (int off = 1; off < 1024; off <<= 1) {
        unsigned int v = (tid >= off) ? ssum[tid - off] : 0u;
        __syncthreads();
        ssum[tid] += v;
        __syncthreads();
    }
    const unsigned int incl = ssum[tid];
    const unsigned int excl = incl - s;
    const unsigned int target = (pass == 1) ? (NPTS - 1)
                                            : (unsigned int)g_target[b];
    if (target >= excl && target < incl) {           // unique owner thread
        // re-read own 64 bins to locate the target bin
        unsigned int rem = target - excl;
        int bin = tid * 64;
        const unsigned int* hb = g_hist + b * NBIN + tid * 64;
        for (int i = 0; i < 64; i++) {
            const unsigned int hv = hb[i];
            if (rem < hv) break;
            rem -= hv; bin++;
        }
        if (pass == 1) {
            g_prefix[b] = (unsigned int)bin;
            g_target[b] = (int)rem;
        } else {
            const unsigned int T = ((unsigned int)g_prefix[b] << 16)
                                 | (unsigned int)(bin & 0xffff);
            g_thresh32[b] = T;
            g_cnt[b] = 0;
            s_T = T;
            s_need = (int)rem + 1;
        }
    }
    __syncthreads();   // owner's locate (reads own bins) done; s_T/s_need set
    // re-zero own 64 bins (disjoint per thread; pass1 -> clean for hist2,
    // pass2 -> clean for next graph replay)
    #pragma unroll
    for (int q = 0; q < 16; q++)
        hist4[tid * 16 + q] = make_uint4(0u, 0u, 0u, 0u);

    if (pass == 2) {
        // ---- exact, index-ordered tie resolution for absbits == T ----
        const unsigned int T = s_T;
        const int need = s_need;
        const float* src = coarse + b * NPIX;
        const int base = tid * 64;
        unsigned long long m = 0ull;
        #pragma unroll
        for (int i = 0; i < 64; i += 4) {
            float4 v = *(const float4*)&src[base + i];
            if (absbits(v.x) == T) m |= 1ull << i;
            if (absbits(v.y) == T) m |= 1ull << (i + 1);
            if (absbits(v.z) == T) m |= 1ull << (i + 2);
            if (absbits(v.w) == T) m |= 1ull << (i + 3);
        }
        const int c = __popcll(m);
        __syncthreads();           // ssum reuse
        ssum[tid] = (unsigned int)c;
        __syncthreads();
        for (int off = 1; off < 1024; off <<= 1) {
            unsigned int v = (tid >= off) ? ssum[tid - off] : 0u;
            __syncthreads();
            ssum[tid] += v;
            __syncthreads();
        }
        int rank = (int)(ssum[tid] - c);   // exclusive prefix = global rank
        while (m && rank < need) {
            int i = __ffsll((long long)m) - 1;
            m &= m - 1;
            g_idx[b * NPTS + (NPTS - need) + rank] = base + i;
            rank++;
        }
    }
}

// ---------------- kernel 5: warp-aggregated compaction (a < T) -----------
__global__ void compact_kernel(const float* __restrict__ coarse) {
    const int i  = blockIdx.x * blockDim.x + threadIdx.x;  // 0..262143
    const int b  = i >> 16;
    const int li = i & 0xffff;
    const bool take = (absbits(coarse[i]) < g_thresh32[b]);
    // warps never straddle a batch (65536 % 32 == 0)
    unsigned mask = __ballot_sync(0xffffffffu, take);
    if (take) {
        const int lane = threadIdx.x & 31;
        const int leader = __ffs(mask) - 1;
        int pos = 0;
        if (lane == leader) pos = atomicAdd(&g_cnt[b], __popc(mask));
        pos = __shfl_sync(0xffffffffu, pos, leader);
        pos += __popc(mask & ((1u << lane) - 1u));
        g_idx[b * NPTS + pos] = li;
    }
}

// ---------------- kernel 6: pipelined sample + MLP + scatter --------------
// 512 threads, occ=1, grid (NPTS/TP/TT, NB) = (32, 4) = 128 blocks.
// Warps 8-15: producers (gather tile k into double-buffered sF).
// Warps 0-7 : consumers (256x64 fp32 register GEMM + epilogue).
// Named barriers: full0=1 full1=2 empty0=3 empty1=4 prod=5 cons=6.
#define SMEM_BYTES ((2 * NFEAT * TP + 32 * TP) * 4 + 2 * TP * 4)

extern __shared__ float smem[];

__global__ __launch_bounds__(512, 1) void main_kernel(
    const float* __restrict__ coarse, const float* __restrict__ fine,
    const float* __restrict__ W1, const float* __restrict__ b1,
    const float* __restrict__ W2, const float* __restrict__ b2,
    float* __restrict__ out)
{
    float* sFbuf[2];
    sFbuf[0] = smem;                           // NFEAT*TP each
    sFbuf[1] = smem + NFEAT * TP;
    float* sPart = smem + 2 * NFEAT * TP;      // 32*TP
    int* sIdxbuf[2];
    sIdxbuf[0] = (int*)(sPart + 32 * TP);
    sIdxbuf[1] = sIdxbuf[0] + TP;

    const int tid   = threadIdx.x;
    const int batch = blockIdx.y;
    const int tile0 = blockIdx.x * TT;

    if (tid >= 256) {
        // ================= PRODUCER (warps 8-15) =================
        const int ptid = tid - 256;
        const int gp   = ptid & (TP - 1);
        const int gc0  = ptid >> 6;            // 0..3
        const float* fbase = fine + (size_t)batch * CCH * HF * WF;
        for (int k = 0; k < TT; k++) {
            const int buf = k & 1;
            float* sF  = sFbuf[buf];
            int* sIdx  = sIdxbuf[buf];
            if (k >= 2)
                asm volatile("bar.sync %0, 512;" :: "r"(3 + buf) : "memory");
            if (ptid < TP)
                sIdx[ptid] = g_idx[batch * NPTS + (tile0 + k) * TP + ptid];
            asm volatile("bar.sync 5, 256;" ::: "memory");   // producer-only
            // bilinear == 0.25 * (2x2 block at (2r, 2c)); .cg bypasses L1
            const int idx = sIdx[gp];
            const int y0 = (idx >> 8) * 2;
            const int x0 = (idx & 255) * 2;
            const float2* pptr = (const float2*)(fbase
                                 + ((size_t)gc0 * HF + y0) * WF + x0);
            float* sdst = sF + gc0 * TP + gp;
            #pragma unroll 8
            for (int c = 0; c < 32; c++) {     // channels gc0, gc0+4, ...
                float2 r0 = __ldcg(pptr);
                float2 r1 = __ldcg(pptr + WF / 2);
                *sdst = 0.25f * ((r0.x + r0.y) + (r1.x + r1.y));
                pptr += (size_t)2 * HF * WF;
                sdst += 4 * TP;
            }
            if (ptid < TP)
                sF[CCH * TP + ptid] = coarse[batch * NPIX + sIdx[ptid]];
            __threadfence_block();
            asm volatile("bar.arrive %0, 512;" :: "r"(1 + buf) : "memory");
        }
    } else {
        // ================= CONSUMER (warps 0-7) =================
        const int hg = tid & 31;       // 32 hidden groups of 8
        const int pg = tid >> 5;       // 8 point groups of 8
        const int h0 = hg * 8;
        const int p0 = pg * 8;
        for (int k = 0; k < TT; k++) {
            const int buf = k & 1;
            const float* sF = sFbuf[buf];
            const int* sIdx = sIdxbuf[buf];
            asm volatile("bar.sync %0, 512;" :: "r"(1 + buf) : "memory");

            float acc[8][8];
            #pragma unroll
            for (int i = 0; i < 8; i++)
                #pragma unroll
                for (int j = 0; j < 8; j++) acc[i][j] = 0.0f;

            for (int f = 0; f < NFEAT; f++) {
                float4 wa = __ldg((const float4*)&W1[f * HID + h0]);
                float4 wb = __ldg((const float4*)&W1[f * HID + h0 + 4]);
                float4 xa = *(const float4*)&sF[f * TP + p0];
                float4 xb = *(const float4*)&sF[f * TP + p0 + 4];
                const float w[8] = {wa.x, wa.y, wa.z, wa.w,
                                    wb.x, wb.y, wb.z, wb.w};
                const float x[8] = {xa.x, xa.y, xa.z, xa.w,
                                    xb.x, xb.y, xb.z, xb.w};
                #pragma unroll
                for (int i = 0; i < 8; i++)
                    #pragma unroll
                    for (int j = 0; j < 8; j++)
                        acc[i][j] += w[i] * x[j];
            }

            float part[8];
            #pragma unroll
            for (int j = 0; j < 8; j++) part[j] = 0.0f;
            #pragma unroll
            for (int i = 0; i < 8; i++) {
                const int h = h0 + i;
                const float b1v = __ldg(&b1[h]);
                const float w2v = __ldg(&W2[h]);
                #pragma unroll
                for (int j = 0; j < 8; j++)
                    part[j] += fmaxf(acc[i][j] + b1v, 0.0f) * w2v;
            }
            #pragma unroll
            for (int j = 0; j < 8; j++)
                sPart[hg * TP + p0 + j] = part[j];
            asm volatile("bar.sync 6, 256;" ::: "memory");   // consumer-only
            if (tid < TP) {
                float r = __ldg(&b2[0]);
                #pragma unroll
                for (int g = 0; g < 32; g++) r += sPart[g * TP + tid];
                out[batch * NPIX + sIdx[tid]] = r;
            }
            asm volatile("bar.sync 6, 256;" ::: "memory");
            asm volatile("bar.arrive %0, 512;" :: "r"(3 + buf) : "memory");
        }
    }
}

// ---------------- launch ---------------------------------------------------
extern "C" void kernel_launch(void* const* d_in, const int* in_sizes, int n_in,
                              void* d_out, int out_size) {
    const float* coarse = (const float*)d_in[0];
    const float* fine   = (const float*)d_in[1];
    const float* W1     = (const float*)d_in[2];
    const float* b1     = (const float*)d_in[3];
    const float* W2     = (const float*)d_in[4];
    const float* b2     = (const float*)d_in[5];
    float* out = (float*)d_out;

    // out = coarse everywhere; refined points overwritten by main_kernel
    cudaMemcpyAsync(out, coarse, (size_t)NB * NPIX * sizeof(float),
                    cudaMemcpyDeviceToDevice, 0);

    hist1_kernel<<<dim3(32, NB), 256>>>(coarse);       // launch 1
    scan_kernel<<<NB, 1024>>>(coarse, 1);              // launch 2
    hist2_kernel<<<dim3(32, NB), 256>>>(coarse);       // launch 3
    scan_kernel<<<NB, 1024>>>(coarse, 2);              // launch 4
    compact_kernel<<<(NB * NPIX) / 256, 256>>>(coarse);// launch 5

    cudaFuncSetAttribute(main_kernel,
                         cudaFuncAttributeMaxDynamicSharedMemorySize,
                         SMEM_BYTES);
    main_kernel<<<dim3(NPTS / TP / TT, NB), 512, SMEM_BYTES>>>(  // launch 6
        coarse, fine, W1, b1, W2, b2, out);
}

// round 14
// speedup vs baseline: 1.3635x; 1.3635x over previous
#include <cuda_runtime.h>
#include <cstdint>

#define NB    4
#define NPIX  65536     // 256*256
#define CCH   128
#define HF    512
#define WF    512
#define NPTS  8192
#define HID   256
#define NFEAT 129
#define TP    64        // points per tile
#define TT    4         // tiles per block (pipelined)
#define NBIN  4096      // 12-bit radix digit

// ---------------- device scratch (no allocations allowed) ----------------
__device__ unsigned long long g_thresh[NB];
__device__ unsigned long long g_prefix[NB];
__device__ int g_target[NB];
__device__ int g_cnt[NB];
__device__ int g_idx[NB * NPTS];
__device__ unsigned int g_hist[NB * NBIN];   // zero at load; scans re-zero

// 48-bit key: (|v| bits << 16) | idx  -> unique, lexicographic (|v|, idx)
// matches jax top_k(-|v|) selection set including stable tie-break.
__device__ __forceinline__ unsigned long long make_key(float v, int i) {
    unsigned int a = __float_as_uint(v) & 0x7fffffffu;
    return (((unsigned long long)a) << 16) | (unsigned int)i;
}

// ---------------- kernel 0: per-call state reset -------------------------
__global__ void init_kernel() {
    int b = threadIdx.x;
    if (b < NB) { g_prefix[b] = 0ull; g_target[b] = NPTS - 1; g_cnt[b] = 0; }
}

// ---------------- kernel 1a: 12-bit radix histogram (smem-staged) --------
__global__ void hist_kernel(const float* __restrict__ coarse, int shift) {
    __shared__ unsigned int s_hist[NBIN];
    const int b   = blockIdx.y;
    const int tid = threadIdx.x;
    for (int i = tid; i < NBIN; i += 256) s_hist[i] = 0u;
    __syncthreads();

    const unsigned long long pref = g_prefix[b];
    const float* src = coarse + b * NPIX;
    const int base = blockIdx.x * 2048;
    #pragma unroll
    for (int j = 0; j < 8; j++) {
        const int i = base + j * 256 + tid;
        unsigned long long k = make_key(src[i], i);
        if ((k >> (shift + 12)) == pref)
            atomicAdd(&s_hist[(unsigned int)(k >> shift) & 0xfffu], 1u);
    }
    __syncthreads();

    unsigned int* hist = g_hist + b * NBIN;
    for (int i = tid; i < NBIN; i += 256) {
        unsigned int v = s_hist[i];
        if (v) atomicAdd(&hist[i], v);
    }
}

// ---------------- kernel 1b: scan 4096 bins (uint4), locate, zero --------
__global__ void scan_kernel(int is_last) {
    __shared__ unsigned int ssum[1024];
    const int b   = blockIdx.x;
    const int tid = threadIdx.x;
    uint4* hist4 = reinterpret_cast<uint4*>(g_hist + b * NBIN);

    const uint4 h = hist4[tid];                      // bins 4*tid .. 4*tid+3
    const unsigned int s = h.x + h.y + h.z + h.w;
    ssum[tid] = s;
    __syncthreads();
    for (int off = 1; off < 1024; off <<= 1) {
        unsigned int v = (tid >= off) ? ssum[tid - off] : 0u;
        __syncthreads();
        ssum[tid] += v;
        __syncthreads();
    }
    const unsigned int incl = ssum[tid];
    const unsigned int excl = incl - s;
    const unsigned int target = (unsigned int)g_target[b];
    if (target >= excl && target < incl) {           // unique owner thread
        unsigned int rem = target - excl;
        int bin = tid * 4;
        unsigned int hv[4] = {h.x, h.y, h.z, h.w};
        #pragma unroll
        for (int i = 0; i < 4; i++) {
            if (rem < hv[i]) break;
            rem -= hv[i]; bin++;
        }
        unsigned long long np = (g_prefix[b] << 12) | (unsigned int)(bin & 0xfff);
        if (is_last) {
            g_thresh[b] = np;
        } else {
            g_prefix[b] = np;
            g_target[b] = (int)rem;
        }
    }
    hist4[tid] = make_uint4(0u, 0u, 0u, 0u);         // replay-safe
}

// ---------------- kernel 2: warp-aggregated compaction -------------------
__global__ void compact_kernel(const float* __restrict__ coarse) {
    const int i = blockIdx.x * blockDim.x + threadIdx.x;   // 0..262143
    const int b  = i >> 16;
    const int li = i & 0xffff;
    unsigned long long k = make_key(coarse[i], li);
    const bool take = (k <= g_thresh[b]);
    // warps never straddle a batch (65536 % 32 == 0)
    unsigned mask = __ballot_sync(0xffffffffu, take);
    if (take) {
        const int lane = threadIdx.x & 31;
        const int leader = __ffs(mask) - 1;
        int pos = 0;
        if (lane == leader) pos = atomicAdd(&g_cnt[b], __popc(mask));
        pos = __shfl_sync(0xffffffffu, pos, leader);
        pos += __popc(mask & ((1u << lane) - 1u));
        g_idx[b * NPTS + pos] = li;
    }
}

// ---------------- kernel 3: pipelined sample + MLP + scatter --------------
// 512 threads, occ=1, grid (NPTS/TP/TT, NB) = (32, 4) = 128 blocks.
// W1 staged ONCE per block into smem (132KB); warps 8-15 gather (double-
// buffered sF), warps 0-7 run the 256x64 fp32 register GEMM from smem.
// Named barriers: full0=1 full1=2 empty0=3 empty1=4 prod=5 cons=6.
#define SMEM_BYTES ((NFEAT * HID + 2 * NFEAT * TP + 32 * TP) * 4 + 2 * TP * 4)

extern __shared__ float smem[];

__global__ __launch_bounds__(512, 1) void main_kernel(
    const float* __restrict__ coarse, const float* __restrict__ fine,
    const float* __restrict__ W1, const float* __restrict__ b1,
    const float* __restrict__ W2, const float* __restrict__ b2,
    float* __restrict__ out)
{
    float* sW1 = smem;                              // 33024 floats
    float* sFbuf[2];
    sFbuf[0] = sW1 + NFEAT * HID;                   // 8256 each
    sFbuf[1] = sFbuf[0] + NFEAT * TP;
    float* sPart = sFbuf[1] + NFEAT * TP;           // 2048
    int* sIdxbuf[2];
    sIdxbuf[0] = (int*)(sPart + 32 * TP);
    sIdxbuf[1] = sIdxbuf[0] + TP;

    const int tid   = threadIdx.x;
    const int batch = blockIdx.y;
    const int tile0 = blockIdx.x * TT;

    // stage W1 once (all 512 threads), reused for all TT tiles
    for (int i = tid; i < NFEAT * HID; i += 512) sW1[i] = W1[i];
    __syncthreads();

    if (tid >= 256) {
        // ================= PRODUCER (warps 8-15) =================
        const int ptid = tid - 256;
        const int gp   = ptid & (TP - 1);
        const int gc0  = ptid >> 6;            // 0..3
        const float* fbase = fine + (size_t)batch * CCH * HF * WF;
        for (int k = 0; k < TT; k++) {
            const int buf = k & 1;
            float* sF  = sFbuf[buf];
            int* sIdx  = sIdxbuf[buf];
            if (k >= 2)
                asm volatile("bar.sync %0, 512;" :: "r"(3 + buf) : "memory");
            if (ptid < TP)
                sIdx[ptid] = g_idx[batch * NPTS + (tile0 + k) * TP + ptid];
            asm volatile("bar.sync 5, 256;" ::: "memory");   // producer-only
            // bilinear == 0.25 * (2x2 block at (2r, 2c)); .cg bypasses L1
            const int idx = sIdx[gp];
            const int y0 = (idx >> 8) * 2;
            const int x0 = (idx & 255) * 2;
            const float2* pptr = (const float2*)(fbase
                                 + ((size_t)gc0 * HF + y0) * WF + x0);
            float* sdst = sF + gc0 * TP + gp;
            #pragma unroll 8
            for (int c = 0; c < 32; c++) {     // channels gc0, gc0+4, ...
                float2 r0 = __ldcg(pptr);
                float2 r1 = __ldcg(pptr + WF / 2);
                *sdst = 0.25f * ((r0.x + r0.y) + (r1.x + r1.y));
                pptr += (size_t)2 * HF * WF;
                sdst += 4 * TP;
            }
            if (ptid < TP)
                sF[CCH * TP + ptid] = coarse[batch * NPIX + sIdx[ptid]];
            __threadfence_block();
            asm volatile("bar.arrive %0, 512;" :: "r"(1 + buf) : "memory");
        }
    } else {
        // ================= CONSUMER (warps 0-7) =================
        const int hg = tid & 31;       // 32 hidden groups of 8
        const int pg = tid >> 5;       // 8 point groups of 8
        const int h0 = hg * 8;
        const int p0 = pg * 8;
        for (int k = 0; k < TT; k++) {
            const int buf = k & 1;
            const float* sF = sFbuf[buf];
            const int* sIdx = sIdxbuf[buf];
            asm volatile("bar.sync %0, 512;" :: "r"(1 + buf) : "memory");

            float acc[8][8];
            #pragma unroll
            for (int i = 0; i < 8; i++)
                #pragma unroll
                for (int j = 0; j < 8; j++) acc[i][j] = 0.0f;

            for (int f = 0; f < NFEAT; f++) {
                float4 wa = *(const float4*)&sW1[f * HID + h0];
                float4 wb = *(const float4*)&sW1[f * HID + h0 + 4];
                float4 xa = *(const float4*)&sF[f * TP + p0];
                float4 xb = *(const float4*)&sF[f * TP + p0 + 4];
                const float w[8] = {wa.x, wa.y, wa.z, wa.w,
                                    wb.x, wb.y, wb.z, wb.w};
                const float x[8] = {xa.x, xa.y, xa.z, xa.w,
                                    xb.x, xb.y, xb.z, xb.w};
                #pragma unroll
                for (int i = 0; i < 8; i++)
                    #pragma unroll
                    for (int j = 0; j < 8; j++)
                        acc[i][j] += w[i] * x[j];
            }

            float part[8];
            #pragma unroll
            for (int j = 0; j < 8; j++) part[j] = 0.0f;
            #pragma unroll
            for (int i = 0; i < 8; i++) {
                const int h = h0 + i;
                const float b1v = __ldg(&b1[h]);
                const float w2v = __ldg(&W2[h]);
                #pragma unroll
                for (int j = 0; j < 8; j++)
                    part[j] += fmaxf(acc[i][j] + b1v, 0.0f) * w2v;
            }
            #pragma unroll
            for (int j = 0; j < 8; j++)
                sPart[hg * TP + p0 + j] = part[j];
            asm volatile("bar.sync 6, 256;" ::: "memory");   // consumer-only
            if (tid < TP) {
                float r = __ldg(&b2[0]);
                #pragma unroll
                for (int g = 0; g < 32; g++) r += sPart[g * TP + tid];
                out[batch * NPIX + sIdx[tid]] = r;
            }
            asm volatile("bar.sync 6, 256;" ::: "memory");
            asm volatile("bar.arrive %0, 512;" :: "r"(3 + buf) : "memory");
        }
    }
}

// ---------------- launch ---------------------------------------------------
extern "C" void kernel_launch(void* const* d_in, const int* in_sizes, int n_in,
                              void* d_out, int out_size) {
    const float* coarse = (const float*)d_in[0];
    const float* fine   = (const float*)d_in[1];
    const float* W1     = (const float*)d_in[2];
    const float* b1     = (const float*)d_in[3];
    const float* W2     = (const float*)d_in[4];
    const float* b2     = (const float*)d_in[5];
    float* out = (float*)d_out;

    // out = coarse everywhere; refined points overwritten by main_kernel
    cudaMemcpyAsync(out, coarse, (size_t)NB * NPIX * sizeof(float),
                    cudaMemcpyDeviceToDevice, 0);

    init_kernel<<<1, 32>>>();

    // 4-pass 12-bit radix select of the rank-8191 48-bit key
    hist_kernel<<<dim3(32, NB), 256>>>(coarse, 36);
    scan_kernel<<<NB, 1024>>>(0);
    hist_kernel<<<dim3(32, NB), 256>>>(coarse, 24);
    scan_kernel<<<NB, 1024>>>(0);
    hist_kernel<<<dim3(32, NB), 256>>>(coarse, 12);
    scan_kernel<<<NB, 1024>>>(0);
    hist_kernel<<<dim3(32, NB), 256>>>(coarse, 0);
    scan_kernel<<<NB, 1024>>>(1);

    compact_kernel<<<(NB * NPIX) / 256, 256>>>(coarse);

    cudaFuncSetAttribute(main_kernel,
                         cudaFuncAttributeMaxDynamicSharedMemorySize,
                         SMEM_BYTES);
    main_kernel<<<dim3(NPTS / TP / TT, NB), 512, SMEM_BYTES>>>(
        coarse, fine, W1, b1, W2, b2, out);
}

// round 16
// speedup vs baseline: 1.4162x; 1.0387x over previous
#include <cuda_runtime.h>
#include <cstdint>

#define NB    4
#define NPIX  65536     // 256*256
#define CCH   128
#define HF    512
#define WF    512
#define NPTS  8192
#define HID   256
#define NFEAT 129
#define TP    64        // points per tile
#define TT    4         // tiles per block (pipelined)
#define NBIN  4096      // 12-bit radix digit

// ---------------- device scratch (no allocations allowed) ----------------
__device__ unsigned int g_prefix[NB];        // bits 30:19 digit after pass 1
__device__ int g_target[NB];                 // rank remainder after pass 1
__device__ int g_idx[NB * NPTS];
__device__ unsigned int g_hist[NB * NBIN];   // zero at load; scan1 re-zeros

__device__ __forceinline__ unsigned int absbits(float v) {
    return __float_as_uint(v) & 0x7fffffffu;
}

// ---------------- kernel 1: 12-bit hist of |v| bits[30:19] (smem) --------
// grid (32, NB) x 256; 8 elems/thread, coalesced. Unconditional (pass 1).
__global__ void hist1_kernel(const float* __restrict__ coarse) {
    __shared__ unsigned int s_hist[NBIN];
    const int b   = blockIdx.y;
    const int tid = threadIdx.x;
    for (int i = tid; i < NBIN; i += 256) s_hist[i] = 0u;
    __syncthreads();

    const float* src = coarse + b * NPIX;
    const int base = blockIdx.x * 2048;
    #pragma unroll
    for (int j = 0; j < 8; j++)
        atomicAdd(&s_hist[absbits(src[base + j * 256 + tid]) >> 19], 1u);
    __syncthreads();

    unsigned int* hist = g_hist + b * NBIN;
    for (int i = tid; i < NBIN; i += 256) {
        unsigned int v = s_hist[i];
        if (v) atomicAdd(&hist[i], v);
    }
}

// ---------------- kernel 2: scan 4096 bins, locate rank 8191, zero -------
// grid NB x 1024. Pass-1 target hardcoded (replay-safe, no init kernel).
__global__ __launch_bounds__(1024, 1) void scan1_kernel() {
    __shared__ unsigned int ssum[1024];
    const int b   = blockIdx.x;
    const int tid = threadIdx.x;
    uint4* hist4 = reinterpret_cast<uint4*>(g_hist + b * NBIN);

    const uint4 h = hist4[tid];                      // bins 4*tid..4*tid+3
    const unsigned int s = h.x + h.y + h.z + h.w;
    ssum[tid] = s;
    __syncthreads();
    for (int off = 1; off < 1024; off <<= 1) {
        unsigned int v = (tid >= off) ? ssum[tid - off] : 0u;
        __syncthreads();
        ssum[tid] += v;
        __syncthreads();
    }
    const unsigned int incl = ssum[tid];
    const unsigned int excl = incl - s;
    const unsigned int target = NPTS - 1;
    if (target >= excl && target < incl) {           // unique owner
        unsigned int rem = target - excl;
        int bin = tid * 4;
        unsigned int hv[4] = {h.x, h.y, h.z, h.w};
        #pragma unroll
        for (int i = 0; i < 4; i++) {
            if (rem < hv[i]) break;
            rem -= hv[i]; bin++;
        }
        g_prefix[b] = (unsigned int)bin;             // bits 30:19 digit
        g_target[b] = (int)rem;
    }
    hist4[tid] = make_uint4(0u, 0u, 0u, 0u);         // replay-safe
}

// ---------------- kernel 3: finish select + full compaction ---------------
// grid NB x 1024 (one block per batch; 64 elems/thread).
// Phase A: 4096-bin hist of bits[18:7] within prefix P -> P2, R2.
// Phase B: 128-bin hist of bits[6:0] within P2 -> exact T, need.
// Phase C: packed block scan writes g_idx exactly:
//   positions [0, NPTS-need): all indices with |v|bits < T (index-ordered)
//   positions [NPTS-need, NPTS): first-by-index `need` with |v|bits == T
// Selection set == jax top_k(-|v|) incl. stable tie-break. Deterministic.
__global__ __launch_bounds__(1024, 1) void final_kernel(
    const float* __restrict__ coarse)
{
    __shared__ __align__(16) unsigned int hist[NBIN];
    __shared__ unsigned int ssum[1024];
    __shared__ unsigned int sP2;
    __shared__ int sR2;
    __shared__ unsigned int sT;
    __shared__ int sNeed;
    const int b   = blockIdx.x;
    const int tid = threadIdx.x;
    const unsigned int P = g_prefix[b];
    const unsigned int R = (unsigned int)g_target[b];
    const float* src = coarse + b * NPIX;
    const int base = tid * 64;

    reinterpret_cast<uint4*>(hist)[tid] = make_uint4(0u, 0u, 0u, 0u);
    __syncthreads();

    // ---- phase A: hist bits[18:7] of prefix-P elements ----
    #pragma unroll
    for (int i = 0; i < 64; i += 4) {
        float4 v = *(const float4*)&src[base + i];
        unsigned int a0 = absbits(v.x), a1 = absbits(v.y);
        unsigned int a2 = absbits(v.z), a3 = absbits(v.w);
        if ((a0 >> 19) == P) atomicAdd(&hist[(a0 >> 7) & 0xfffu], 1u);
        if ((a1 >> 19) == P) atomicAdd(&hist[(a1 >> 7) & 0xfffu], 1u);
        if ((a2 >> 19) == P) atomicAdd(&hist[(a2 >> 7) & 0xfffu], 1u);
        if ((a3 >> 19) == P) atomicAdd(&hist[(a3 >> 7) & 0xfffu], 1u);
    }
    __syncthreads();
    const uint4 h = reinterpret_cast<uint4*>(hist)[tid];
    const unsigned int s = h.x + h.y + h.z + h.w;
    ssum[tid] = s;
    __syncthreads();
    for (int off = 1; off < 1024; off <<= 1) {
        unsigned int v = (tid >= off) ? ssum[tid - off] : 0u;
        __syncthreads();
        ssum[tid] += v;
        __syncthreads();
    }
    {
        const unsigned int incl = ssum[tid];
        const unsigned int excl = incl - s;
        if (R >= excl && R < incl) {                 // unique owner
            unsigned int rem = R - excl;
            int bin = tid * 4;
            unsigned int hv[4] = {h.x, h.y, h.z, h.w};
            #pragma unroll
            for (int i = 0; i < 4; i++) {
                if (rem < hv[i]) break;
                rem -= hv[i]; bin++;
            }
            sP2 = (P << 12) | (unsigned int)(bin & 0xfff);   // == a>>7
            sR2 = (int)rem;
        }
    }
    __syncthreads();

    // ---- phase B: 128-bin residual hist within P2; masks for C ----
    if (tid < 128) hist[tid] = 0u;
    __syncthreads();
    const unsigned int P2 = sP2;
    unsigned long long m_below = 0ull, m_in = 0ull;
    #pragma unroll
    for (int i = 0; i < 64; i += 4) {
        float4 v = *(const float4*)&src[base + i];
        unsigned int a[4] = {absbits(v.x), absbits(v.y),
                             absbits(v.z), absbits(v.w)};
        #pragma unroll
        for (int j = 0; j < 4; j++) {
            const unsigned int p = a[j] >> 7;
            if (p < P2) m_below |= 1ull << (i + j);
            else if (p == P2) {
                m_in |= 1ull << (i + j);
                atomicAdd(&hist[a[j] & 0x7fu], 1u);
            }
        }
    }
    __syncthreads();
    if (tid == 0) {
        unsigned int r = (unsigned int)sR2;
        int bin = 0;
        for (; bin < 128; bin++) {
            const unsigned int hv = hist[bin];
            if (r < hv) break;
            r -= hv;
        }
        sT = (P2 << 7) | (unsigned int)bin;          // exact threshold bits
        sNeed = (int)r + 1;
    }
    __syncthreads();
    const int need = sNeed;
    const unsigned int bin3 = sT & 0x7fu;

    // ---- phase C: classify in-bin elems (sparse re-read), scan, write ----
    unsigned long long m_lt = m_below, m_eq = 0ull;
    {
        unsigned long long m = m_in;
        while (m) {
            const int i = __ffsll((long long)m) - 1;
            m &= m - 1;
            const unsigned int r = absbits(src[base + i]) & 0x7fu;
            if (r < bin3)       m_lt |= 1ull << i;
            else if (r == bin3) m_eq |= 1ull << i;
        }
    }
    const int c_lt = __popcll(m_lt);
    const int c_eq = __popcll(m_eq);
    const unsigned int packed = ((unsigned int)c_lt << 17) | (unsigned int)c_eq;
    __syncthreads();
    ssum[tid] = packed;
    __syncthreads();
    for (int off = 1; off < 1024; off <<= 1) {
        unsigned int v = (tid >= off) ? ssum[tid - off] : 0u;
        __syncthreads();
        ssum[tid] += v;
        __syncthreads();
    }
    const unsigned int excl2 = ssum[tid] - packed;
    int lt_rank = (int)(excl2 >> 17);
    int eq_rank = (int)(excl2 & 0x1ffffu);
    while (m_lt) {
        const int i = __ffsll((long long)m_lt) - 1;
        m_lt &= m_lt - 1;
        g_idx[b * NPTS + lt_rank++] = base + i;
    }
    while (m_eq) {
        const int i = __ffsll((long long)m_eq) - 1;
        m_eq &= m_eq - 1;
        if (eq_rank < need)
            g_idx[b * NPTS + (NPTS - need) + eq_rank] = base + i;
        eq_rank++;
    }
}

// ---------------- kernel 4: pipelined sample + MLP + scatter --------------
// (R14 main, verbatim — proven.) 512 threads, occ=1, grid (32, 4).
#define SMEM_BYTES ((NFEAT * HID + 2 * NFEAT * TP + 32 * TP) * 4 + 2 * TP * 4)

extern __shared__ float smem[];

__global__ __launch_bounds__(512, 1) void main_kernel(
    const float* __restrict__ coarse, const float* __restrict__ fine,
    const float* __restrict__ W1, const float* __restrict__ b1,
    const float* __restrict__ W2, const float* __restrict__ b2,
    float* __restrict__ out)
{
    float* sW1 = smem;                              // 33024 floats
    float* sFbuf[2];
    sFbuf[0] = sW1 + NFEAT * HID;                   // 8256 each
    sFbuf[1] = sFbuf[0] + NFEAT * TP;
    float* sPart = sFbuf[1] + NFEAT * TP;           // 2048
    int* sIdxbuf[2];
    sIdxbuf[0] = (int*)(sPart + 32 * TP);
    sIdxbuf[1] = sIdxbuf[0] + TP;

    const int tid   = threadIdx.x;
    const int batch = blockIdx.y;
    const int tile0 = blockIdx.x * TT;

    for (int i = tid; i < NFEAT * HID; i += 512) sW1[i] = W1[i];
    __syncthreads();

    if (tid >= 256) {
        // ================= PRODUCER (warps 8-15) =================
        const int ptid = tid - 256;
        const int gp   = ptid & (TP - 1);
        const int gc0  = ptid >> 6;            // 0..3
        const float* fbase = fine + (size_t)batch * CCH * HF * WF;
        for (int k = 0; k < TT; k++) {
            const int buf = k & 1;
            float* sF  = sFbuf[buf];
            int* sIdx  = sIdxbuf[buf];
            if (k >= 2)
                asm volatile("bar.sync %0, 512;" :: "r"(3 + buf) : "memory");
            if (ptid < TP)
                sIdx[ptid] = g_idx[batch * NPTS + (tile0 + k) * TP + ptid];
            asm volatile("bar.sync 5, 256;" ::: "memory");   // producer-only
            const int idx = sIdx[gp];
            const int y0 = (idx >> 8) * 2;
            const int x0 = (idx & 255) * 2;
            const float2* pptr = (const float2*)(fbase
                                 + ((size_t)gc0 * HF + y0) * WF + x0);
            float* sdst = sF + gc0 * TP + gp;
            #pragma unroll 8
            for (int c = 0; c < 32; c++) {     // channels gc0, gc0+4, ...
                float2 r0 = __ldcg(pptr);
                float2 r1 = __ldcg(pptr + WF / 2);
                *sdst = 0.25f * ((r0.x + r0.y) + (r1.x + r1.y));
                pptr += (size_t)2 * HF * WF;
                sdst += 4 * TP;
            }
            if (ptid < TP)
                sF[CCH * TP + ptid] = coarse[batch * NPIX + sIdx[ptid]];
            __threadfence_block();
            asm volatile("bar.arrive %0, 512;" :: "r"(1 + buf) : "memory");
        }
    } else {
        // ================= CONSUMER (warps 0-7) =================
        const int hg = tid & 31;
        const int pg = tid >> 5;
        const int h0 = hg * 8;
        const int p0 = pg * 8;
        for (int k = 0; k < TT; k++) {
            const int buf = k & 1;
            const float* sF = sFbuf[buf];
            const int* sIdx = sIdxbuf[buf];
            asm volatile("bar.sync %0, 512;" :: "r"(1 + buf) : "memory");

            float acc[8][8];
            #pragma unroll
            for (int i = 0; i < 8; i++)
                #pragma unroll
                for (int j = 0; j < 8; j++) acc[i][j] = 0.0f;

            for (int f = 0; f < NFEAT; f++) {
                float4 wa = *(const float4*)&sW1[f * HID + h0];
                float4 wb = *(const float4*)&sW1[f * HID + h0 + 4];
                float4 xa = *(const float4*)&sF[f * TP + p0];
                float4 xb = *(const float4*)&sF[f * TP + p0 + 4];
                const float w[8] = {wa.x, wa.y, wa.z, wa.w,
                                    wb.x, wb.y, wb.z, wb.w};
                const float x[8] = {xa.x, xa.y, xa.z, xa.w,
                                    xb.x, xb.y, xb.z, xb.w};
                #pragma unroll
                for (int i = 0; i < 8; i++)
                    #pragma unroll
                    for (int j = 0; j < 8; j++)
                        acc[i][j] += w[i] * x[j];
            }

            float part[8];
            #pragma unroll
            for (int j = 0; j < 8; j++) part[j] = 0.0f;
            #pragma unroll
            for (int i = 0; i < 8; i++) {
                const int h = h0 + i;
                const float b1v = __ldg(&b1[h]);
                const float w2v = __ldg(&W2[h]);
                #pragma unroll
                for (int j = 0; j < 8; j++)
                    part[j] += fmaxf(acc[i][j] + b1v, 0.0f) * w2v;
            }
            #pragma unroll
            for (int j = 0; j < 8; j++)
                sPart[hg * TP + p0 + j] = part[j];
            asm volatile("bar.sync 6, 256;" ::: "memory");   // consumer-only
            if (tid < TP) {
                float r = __ldg(&b2[0]);
                #pragma unroll
                for (int g = 0; g < 32; g++) r += sPart[g * TP + tid];
                out[batch * NPIX + sIdx[tid]] = r;
            }
            asm volatile("bar.sync 6, 256;" ::: "memory");
            asm volatile("bar.arrive %0, 512;" :: "r"(3 + buf) : "memory");
        }
    }
}

// ---------------- launch ---------------------------------------------------
extern "C" void kernel_launch(void* const* d_in, const int* in_sizes, int n_in,
                              void* d_out, int out_size) {
    const float* coarse = (const float*)d_in[0];
    const float* fine   = (const float*)d_in[1];
    const float* W1     = (const float*)d_in[2];
    const float* b1     = (const float*)d_in[3];
    const float* W2     = (const float*)d_in[4];
    const float* b2     = (const float*)d_in[5];
    float* out = (float*)d_out;

    // out = coarse everywhere; refined points overwritten by main_kernel
    cudaMemcpyAsync(out, coarse, (size_t)NB * NPIX * sizeof(float),
                    cudaMemcpyDeviceToDevice, 0);

    hist1_kernel<<<dim3(32, NB), 256>>>(coarse);   // kernel 1
    scan1_kernel<<<NB, 1024>>>();                  // kernel 2
    final_kernel<<<NB, 1024>>>(coarse);            // kernel 3

    cudaFuncSetAttribute(main_kernel,
                         cudaFuncAttributeMaxDynamicSharedMemorySize,
                         SMEM_BYTES);
    main_kernel<<<dim3(NPTS / TP / TT, NB), 512, SMEM_BYTES>>>(  // kernel 4
        coarse, fine, W1, b1, W2, b2, out);
}